// round 4
// baseline (speedup 1.0000x reference)
#include <cuda_runtime.h>
#include <math.h>
#include <float.h>

// ---------------------------------------------------------------------------
// ConvKAN3D fused pipeline, R3:
//  - weights pre-packed as u64 {w,w} in shared memory (kills per-tap ALU packs)
//  - dynamic smem so block3 keeps CTILE=4 with packed weights (55.3 KB)
// ---------------------------------------------------------------------------

using u64 = unsigned long long;

__device__ __forceinline__ u64 pk2(float lo, float hi) {
    u64 r; asm("mov.b64 %0,{%1,%2};" : "=l"(r) : "f"(lo), "f"(hi)); return r;
}
__device__ __forceinline__ void up2(u64 v, float& lo, float& hi) {
    asm("mov.b64 {%0,%1}, %2;" : "=f"(lo), "=f"(hi) : "l"(v));
}
__device__ __forceinline__ void ffma2(u64& d, u64 a, u64 b) {
    asm("fma.rn.f32x2 %0, %1, %2, %0;" : "+l"(d) : "l"(a), "l"(b));
}
__device__ __forceinline__ u64 midp(u64 A, u64 B) {
    float al, ah, bl, bh; up2(A, al, ah); up2(B, bl, bh); return pk2(ah, bl);
}

// Padded scratch (zero-initialized device globals; halos never written).
__device__ __align__(16) float g_xp [2u * 66u * 66u * 66u];          // 2.3 MB
__device__ __align__(16) float g_s1p[2u * 32u * 34u * 34u * 34u];    // 10 MB
__device__ __align__(16) float g_s2p[2u * 64u * 18u * 18u * 18u];    // 3 MB
__device__ __align__(16) float g_s3 [2u * 128u * 512u];              // 0.5 MB
__device__ float4 g_coef[224 * 11];
__device__ float  g_mean[2 * 128];

// --- piecewise cubic coefficients (prefix sums of relu(y-t)^3 expansion) ---
__global__ void coef_kernel(const float* __restrict__ k1, const float* __restrict__ sw1,
                            const float* __restrict__ k2, const float* __restrict__ sw2,
                            const float* __restrict__ k3, const float* __restrict__ sw3)
{
    const int t = threadIdx.x;
    if (t >= 224) return;
    const float* kn; const float* sw;
    if (t < 32)       { kn = k1; sw = sw1 + t * 10; }
    else if (t < 96)  { kn = k2; sw = sw2 + (t - 32) * 10; }
    else              { kn = k3; sw = sw3 + (t - 96) * 10; }

    float4 a = make_float4(0.f, 0.f, 0.f, 0.f);
    g_coef[t * 11 + 0] = a;
    for (int e = 1; e <= 10; ++e) {
        const float tk = kn[e - 1];
        const float s  = sw[e - 1];
        a.x = fmaf(-s * tk * tk, tk, a.x);
        a.y = fmaf(3.f * s * tk, tk, a.y);
        a.z = fmaf(-3.f * s, tk, a.z);
        a.w += s;
        g_coef[t * 11 + e] = a;
    }
}

// --- copy x into padded buffer ---------------------------------------------
__global__ void pad_x_kernel(const float* __restrict__ x)
{
    const int idx = blockIdx.x * blockDim.x + threadIdx.x;   // 2*64^3
    if (idx >= 2 * 262144) return;
    const int ix = idx & 63, iy = (idx >> 6) & 63, iz = (idx >> 12) & 63;
    const int b  = idx >> 18;
    g_xp[(((size_t)b * 66 + iz + 1) * 66 + iy + 1) * 66 + ix + 1] = x[idx];
}

// --- pointwise epilogue helper ---------------------------------------------
__device__ __forceinline__ float pointwise(float y, const float4* coef,
                                           float w1, float w2, float scale, float beta)
{
    int e = __float2int_rd((y + 1.0f) * 4.5f) + 1;
    e = max(0, min(10, e));
    const float4 cf = coef[e];
    const float sp  = fmaf(fmaf(fmaf(cf.w, y, cf.z), y, cf.y), y, cf.x);
    const float sig = 1.0f / (1.0f + __expf(-y));
    return fmaf(w1 * sp + w2 * (y * sig), scale, beta);
}

// --- Block 1: CIN=1, all 32 channels per thread -----------------------------
__global__ void __launch_bounds__(128)
block1_kernel(const float* __restrict__ cw,   // [32,1,27]
              const float* __restrict__ cb,
              const float* __restrict__ w1p, const float* __restrict__ w2p,
              const float* __restrict__ gp,  const float* __restrict__ bp,
              float* __restrict__ out)        // padded [2,32,34^3]
{
    constexpr int Din = 66, P = 32, Pq = 34;

    __shared__ u64    s_w[32 * 27];            // packed {w,w}
    __shared__ float4 s_coef[32 * 11];
    __shared__ float  s_bias[32], s_w1[32], s_w2[32], s_scale[32], s_beta[32];

    for (int i = threadIdx.x; i < 32 * 27; i += 128) {
        const float w = cw[i];
        s_w[i] = pk2(w, w);
    }
    for (int i = threadIdx.x; i < 32 * 11; i += 128) s_coef[i] = g_coef[i];
    if (threadIdx.x < 32) {
        const int c = threadIdx.x;
        s_bias[c]  = cb[c];  s_w1[c] = w1p[c];  s_w2[c] = w2p[c];
        s_scale[c] = gp[c] * rsqrtf(1.0f + 1e-5f);  s_beta[c] = bp[c];
    }
    __syncthreads();

    const int vox = blockIdx.x * 128 + threadIdx.x;   // 0..32767
    const int b   = blockIdx.z;
    const int px = vox % P, py = (vox / P) % P, pz = vox / (P * P);

    const u64* inb = (const u64*)(g_xp + (size_t)b * Din * Din * Din);
    const int ib2  = (((2 * pz) * Din + 2 * py) * Din + 2 * px) >> 1;

    u64 A[16], Bv[16], M[16];
    #pragma unroll
    for (int a = 0; a < 4; ++a)
        #pragma unroll
        for (int r = 0; r < 4; ++r) {
            const int o = ib2 + ((((a)*Din + r) * Din) >> 1);
            A[a * 4 + r]  = inb[o];
            Bv[a * 4 + r] = inb[o + 1];
        }
    #pragma unroll
    for (int i = 0; i < 16; ++i) M[i] = midp(A[i], Bv[i]);

    #pragma unroll 1
    for (int c = 0; c < 32; ++c) {
        const float bi = s_bias[c];
        u64 acc[4];
        #pragma unroll
        for (int j = 0; j < 4; ++j) acc[j] = pk2(bi, bi);

        const u64* wp = s_w + c * 27;
        #pragma unroll
        for (int tap = 0; tap < 27; ++tap) {
            const int kd = tap / 9, kh = (tap / 3) % 3, kw = tap % 3;
            const u64 ww = wp[tap];
            #pragma unroll
            for (int dz = 0; dz < 2; ++dz)
                #pragma unroll
                for (int dy = 0; dy < 2; ++dy) {
                    const int ri = (dz + kd) * 4 + dy + kh;
                    const u64 src = (kw == 0) ? A[ri] : (kw == 2) ? Bv[ri] : M[ri];
                    ffma2(acc[dz * 2 + dy], ww, src);
                }
        }

        float mv = -FLT_MAX;
        #pragma unroll
        for (int j = 0; j < 4; ++j) {
            float y0, y1; up2(acc[j], y0, y1);
            mv = fmaxf(mv, pointwise(y0, s_coef + c * 11, s_w1[c], s_w2[c], s_scale[c], s_beta[c]));
            mv = fmaxf(mv, pointwise(y1, s_coef + c * 11, s_w1[c], s_w2[c], s_scale[c], s_beta[c]));
        }
        out[((((size_t)b * 32 + c) * Pq + pz + 1) * Pq + py + 1) * Pq + px + 1] = mv;
    }
}

// --- Generic fused block (blocks 2 & 3); weights in DYNAMIC smem ------------
template<int CIN, int D, int CTILE, int COUT, bool PADOUT>
__global__ void __launch_bounds__(128)
conv_block(const float* __restrict__ in,     // padded [2,CIN,(D+2)^3]
           const float* __restrict__ cw,     // [COUT,CIN,27]
           const float* __restrict__ cb,
           const float* __restrict__ w1p, const float* __restrict__ w2p,
           const float* __restrict__ gp,  const float* __restrict__ bp,
           float* __restrict__ out, int coefBase)
{
    constexpr int Din = D + 2;
    constexpr int P = D / 2, Pq = P + 2, NV = P * P * P;

    const int cobase = blockIdx.y * CTILE;
    const int b      = blockIdx.z;

    extern __shared__ u64 s_w[];               // [ci][tap][t] packed {w,w}
    __shared__ float4 s_coef[CTILE * 11];
    __shared__ float  s_bias[CTILE], s_w1[CTILE], s_w2[CTILE],
                      s_scale[CTILE], s_beta[CTILE];

    for (int i = threadIdx.x; i < CIN * 27 * CTILE; i += 128) {
        const int t   = i % CTILE;
        const int tap = (i / CTILE) % 27;
        const int ci  = i / (CTILE * 27);
        const float w = cw[((size_t)(cobase + t) * CIN + ci) * 27 + tap];
        s_w[i] = pk2(w, w);
    }
    for (int i = threadIdx.x; i < CTILE * 11; i += 128)
        s_coef[i] = g_coef[(coefBase + cobase) * 11 + i];
    if (threadIdx.x < CTILE) {
        const int c = cobase + threadIdx.x;
        s_bias[threadIdx.x]  = cb[c];
        s_w1[threadIdx.x]    = w1p[c];
        s_w2[threadIdx.x]    = w2p[c];
        s_scale[threadIdx.x] = gp[c] * rsqrtf(1.0f + 1e-5f);
        s_beta[threadIdx.x]  = bp[c];
    }
    __syncthreads();

    const int vox = blockIdx.x * 128 + threadIdx.x;
    const int px = vox % P, py = (vox / P) % P, pz = vox / (P * P);

    u64 acc[CTILE][4];
    #pragma unroll
    for (int t = 0; t < CTILE; ++t) {
        const float bi = s_bias[t];
        const u64 bb = pk2(bi, bi);
        #pragma unroll
        for (int j = 0; j < 4; ++j) acc[t][j] = bb;
    }

    const u64* inb = (const u64*)(in + (size_t)b * CIN * Din * Din * Din);
    int ib2 = (((2 * pz) * Din + 2 * py) * Din + 2 * px) >> 1;

    #pragma unroll 1
    for (int ci = 0; ci < CIN; ++ci) {
        u64 A[16], Bv[16], M[16];
        #pragma unroll
        for (int a = 0; a < 4; ++a)
            #pragma unroll
            for (int r = 0; r < 4; ++r) {
                const int o = ib2 + (((a * Din + r) * Din) >> 1);
                A[a * 4 + r]  = inb[o];
                Bv[a * 4 + r] = inb[o + 1];
            }
        #pragma unroll
        for (int i = 0; i < 16; ++i) M[i] = midp(A[i], Bv[i]);

        const u64* wp = s_w + ci * 27 * CTILE;
        #pragma unroll
        for (int tap = 0; tap < 27; ++tap) {
            const int kd = tap / 9, kh = (tap / 3) % 3, kw = tap % 3;
            #pragma unroll
            for (int t = 0; t < CTILE; ++t) {
                const u64 ww = wp[tap * CTILE + t];
                #pragma unroll
                for (int dz = 0; dz < 2; ++dz)
                    #pragma unroll
                    for (int dy = 0; dy < 2; ++dy) {
                        const int ri = (dz + kd) * 4 + dy + kh;
                        const u64 src = (kw == 0) ? A[ri] : (kw == 2) ? Bv[ri] : M[ri];
                        ffma2(acc[t][dz * 2 + dy], ww, src);
                    }
            }
        }
        ib2 += (Din * Din * Din) >> 1;
    }

    #pragma unroll
    for (int t = 0; t < CTILE; ++t) {
        float mv = -FLT_MAX;
        #pragma unroll
        for (int j = 0; j < 4; ++j) {
            float y0, y1; up2(acc[t][j], y0, y1);
            mv = fmaxf(mv, pointwise(y0, s_coef + t * 11, s_w1[t], s_w2[t], s_scale[t], s_beta[t]));
            mv = fmaxf(mv, pointwise(y1, s_coef + t * 11, s_w1[t], s_w2[t], s_scale[t], s_beta[t]));
        }
        const int c = cobase + t;
        if (PADOUT)
            out[((((size_t)b * COUT + c) * Pq + pz + 1) * Pq + py + 1) * Pq + px + 1] = mv;
        else
            out[((size_t)b * COUT + c) * NV + vox] = mv;
    }
}

// --- Head -------------------------------------------------------------------
__global__ void __launch_bounds__(64)
mean_kernel(const float* __restrict__ s3)
{
    const int bc = blockIdx.x;
    const int t  = threadIdx.x;
    const float* p = s3 + (size_t)bc * 512;

    float s = 0.0f;
    #pragma unroll
    for (int i = 0; i < 8; ++i) s += p[t + i * 64];
    #pragma unroll
    for (int off = 16; off > 0; off >>= 1)
        s += __shfl_down_sync(0xffffffffu, s, off);
    __shared__ float part[2];
    if ((t & 31) == 0) part[t >> 5] = s;
    __syncthreads();
    if (t == 0) g_mean[bc] = (part[0] + part[1]) * (1.0f / 512.0f);
}

__global__ void __launch_bounds__(256)
fc_kernel(const float* __restrict__ fc1w, const float* __restrict__ fc1b,
          const float* __restrict__ fc2w, const float* __restrict__ fc2b,
          float* __restrict__ out)
{
    const int t = threadIdx.x;
    __shared__ float m[2][128];
    __shared__ float h[2][256];

    if (t < 128) { m[0][t] = g_mean[t]; m[1][t] = g_mean[128 + t]; }
    __syncthreads();

    #pragma unroll
    for (int b = 0; b < 2; ++b) {
        float s = fc1b[t];
        const float* w = fc1w + t * 128;
        #pragma unroll 8
        for (int k = 0; k < 128; ++k) s = fmaf(m[b][k], w[k], s);
        h[b][t] = fmaxf(s, 0.0f);
    }
    __syncthreads();

    if (t < 4) {
        const int b = t >> 1, o = t & 1;
        float s = fc2b[o];
        const float* w = fc2w + o * 256;
        #pragma unroll 8
        for (int k = 0; k < 256; ++k) s = fmaf(h[b][k], w[k], s);
        out[b * 2 + o] = s;
    }
}

extern "C" void kernel_launch(void* const* d_in, const int* in_sizes, int n_in,
                              void* d_out, int out_size)
{
    (void)in_sizes; (void)n_in; (void)out_size;

    const float* x     = (const float*)d_in[0];
    const float* c1_w  = (const float*)d_in[1];
    const float* c1_b  = (const float*)d_in[2];
    const float* c1_k  = (const float*)d_in[3];
    const float* c1_sw = (const float*)d_in[4];
    const float* c1_w1 = (const float*)d_in[5];
    const float* c1_w2 = (const float*)d_in[6];
    const float* bn1_g = (const float*)d_in[7];
    const float* bn1_b = (const float*)d_in[8];
    const float* c2_w  = (const float*)d_in[9];
    const float* c2_b  = (const float*)d_in[10];
    const float* c2_k  = (const float*)d_in[11];
    const float* c2_sw = (const float*)d_in[12];
    const float* c2_w1 = (const float*)d_in[13];
    const float* c2_w2 = (const float*)d_in[14];
    const float* bn2_g = (const float*)d_in[15];
    const float* bn2_b = (const float*)d_in[16];
    const float* c3_w  = (const float*)d_in[17];
    const float* c3_b  = (const float*)d_in[18];
    const float* c3_k  = (const float*)d_in[19];
    const float* c3_sw = (const float*)d_in[20];
    const float* c3_w1 = (const float*)d_in[21];
    const float* c3_w2 = (const float*)d_in[22];
    const float* bn3_g = (const float*)d_in[23];
    const float* bn3_b = (const float*)d_in[24];
    const float* fc1_w = (const float*)d_in[25];
    const float* fc1_b = (const float*)d_in[26];
    const float* fc2_w = (const float*)d_in[27];
    const float* fc2_b = (const float*)d_in[28];
    float* out = (float*)d_out;

    float *s1p, *s2p, *s3;
    cudaGetSymbolAddress((void**)&s1p, g_s1p);
    cudaGetSymbolAddress((void**)&s2p, g_s2p);
    cudaGetSymbolAddress((void**)&s3,  g_s3);

    // dynamic smem sizes for packed weights
    const int smem2 = 32 * 27 * 4 * (int)sizeof(u64);   // 27648
    const int smem3 = 64 * 27 * 4 * (int)sizeof(u64);   // 55296
    cudaFuncSetAttribute(conv_block<32, 32, 4, 64, true>,
                         cudaFuncAttributeMaxDynamicSharedMemorySize, smem2);
    cudaFuncSetAttribute(conv_block<64, 16, 4, 128, false>,
                         cudaFuncAttributeMaxDynamicSharedMemorySize, smem3);

    coef_kernel<<<1, 224>>>(c1_k, c1_sw, c2_k, c2_sw, c3_k, c3_sw);
    pad_x_kernel<<<(2 * 262144 + 255) / 256, 256>>>(x);

    block1_kernel<<<dim3(32768 / 128, 1, 2), 128>>>(
        c1_w, c1_b, c1_w1, c1_w2, bn1_g, bn1_b, s1p);

    conv_block<32, 32, 4, 64, true><<<dim3(4096 / 128, 64 / 4, 2), 128, smem2>>>(
        s1p, c2_w, c2_b, c2_w1, c2_w2, bn2_g, bn2_b, s2p, 32);

    conv_block<64, 16, 4, 128, false><<<dim3(512 / 128, 128 / 4, 2), 128, smem3>>>(
        s2p, c3_w, c3_b, c3_w1, c3_w2, bn3_g, bn3_b, s3, 96);

    mean_kernel<<<256, 64>>>(s3);
    fc_kernel<<<1, 256>>>(fc1_w, fc1_b, fc2_w, fc2_b, out);
}

// round 5
// speedup vs baseline: 1.0815x; 1.0815x over previous
#include <cuda_runtime.h>
#include <math.h>
#include <float.h>

// ---------------------------------------------------------------------------
// ConvKAN3D fused pipeline, R4:
//  - revert conv_block weight path to R2 (smem float4 + ALU MOV packs)
//  - L1 prefetch of next-ci input patch (hides L2 latency at the ci boundary)
// ---------------------------------------------------------------------------

using u64 = unsigned long long;

__device__ __forceinline__ u64 pk2(float lo, float hi) {
    u64 r; asm("mov.b64 %0,{%1,%2};" : "=l"(r) : "f"(lo), "f"(hi)); return r;
}
__device__ __forceinline__ void up2(u64 v, float& lo, float& hi) {
    asm("mov.b64 {%0,%1}, %2;" : "=f"(lo), "=f"(hi) : "l"(v));
}
__device__ __forceinline__ void ffma2(u64& d, u64 a, u64 b) {
    asm("fma.rn.f32x2 %0, %1, %2, %0;" : "+l"(d) : "l"(a), "l"(b));
}
__device__ __forceinline__ u64 midp(u64 A, u64 B) {
    float al, ah, bl, bh; up2(A, al, ah); up2(B, bl, bh); return pk2(ah, bl);
}
__device__ __forceinline__ void pf_l1(const void* p) {
    asm volatile("prefetch.global.L1 [%0];" :: "l"(p));
}

// Padded scratch (zero-initialized device globals; halos never written).
__device__ __align__(16) float g_xp [2u * 66u * 66u * 66u];          // 2.3 MB
__device__ __align__(16) float g_s1p[2u * 32u * 34u * 34u * 34u];    // 10 MB
__device__ __align__(16) float g_s2p[2u * 64u * 18u * 18u * 18u];    // 3 MB
__device__ __align__(16) float g_s3 [2u * 128u * 512u];              // 0.5 MB
__device__ float4 g_coef[224 * 11];
__device__ float  g_mean[2 * 128];

// --- piecewise cubic coefficients -------------------------------------------
__global__ void coef_kernel(const float* __restrict__ k1, const float* __restrict__ sw1,
                            const float* __restrict__ k2, const float* __restrict__ sw2,
                            const float* __restrict__ k3, const float* __restrict__ sw3)
{
    const int t = threadIdx.x;
    if (t >= 224) return;
    const float* kn; const float* sw;
    if (t < 32)       { kn = k1; sw = sw1 + t * 10; }
    else if (t < 96)  { kn = k2; sw = sw2 + (t - 32) * 10; }
    else              { kn = k3; sw = sw3 + (t - 96) * 10; }

    float4 a = make_float4(0.f, 0.f, 0.f, 0.f);
    g_coef[t * 11 + 0] = a;
    for (int e = 1; e <= 10; ++e) {
        const float tk = kn[e - 1];
        const float s  = sw[e - 1];
        a.x = fmaf(-s * tk * tk, tk, a.x);
        a.y = fmaf(3.f * s * tk, tk, a.y);
        a.z = fmaf(-3.f * s, tk, a.z);
        a.w += s;
        g_coef[t * 11 + e] = a;
    }
}

// --- copy x into padded buffer ----------------------------------------------
__global__ void pad_x_kernel(const float* __restrict__ x)
{
    const int idx = blockIdx.x * blockDim.x + threadIdx.x;   // 2*64^3
    if (idx >= 2 * 262144) return;
    const int ix = idx & 63, iy = (idx >> 6) & 63, iz = (idx >> 12) & 63;
    const int b  = idx >> 18;
    g_xp[(((size_t)b * 66 + iz + 1) * 66 + iy + 1) * 66 + ix + 1] = x[idx];
}

// --- pointwise epilogue helper ----------------------------------------------
__device__ __forceinline__ float pointwise(float y, const float4* coef,
                                           float w1, float w2, float scale, float beta)
{
    int e = __float2int_rd((y + 1.0f) * 4.5f) + 1;
    e = max(0, min(10, e));
    const float4 cf = coef[e];
    const float sp  = fmaf(fmaf(fmaf(cf.w, y, cf.z), y, cf.y), y, cf.x);
    const float sig = 1.0f / (1.0f + __expf(-y));
    return fmaf(w1 * sp + w2 * (y * sig), scale, beta);
}

// --- Block 1: CIN=1, all 32 channels per thread ------------------------------
__global__ void __launch_bounds__(128)
block1_kernel(const float* __restrict__ cw,   // [32,1,27]
              const float* __restrict__ cb,
              const float* __restrict__ w1p, const float* __restrict__ w2p,
              const float* __restrict__ gp,  const float* __restrict__ bp,
              float* __restrict__ out)        // padded [2,32,34^3]
{
    constexpr int Din = 66, P = 32, Pq = 34;

    __shared__ u64    s_w[32 * 27];            // packed {w,w}
    __shared__ float4 s_coef[32 * 11];
    __shared__ float  s_bias[32], s_w1[32], s_w2[32], s_scale[32], s_beta[32];

    for (int i = threadIdx.x; i < 32 * 27; i += 128) {
        const float w = cw[i];
        s_w[i] = pk2(w, w);
    }
    for (int i = threadIdx.x; i < 32 * 11; i += 128) s_coef[i] = g_coef[i];
    if (threadIdx.x < 32) {
        const int c = threadIdx.x;
        s_bias[c]  = cb[c];  s_w1[c] = w1p[c];  s_w2[c] = w2p[c];
        s_scale[c] = gp[c] * rsqrtf(1.0f + 1e-5f);  s_beta[c] = bp[c];
    }
    __syncthreads();

    const int vox = blockIdx.x * 128 + threadIdx.x;   // 0..32767
    const int b   = blockIdx.z;
    const int px = vox % P, py = (vox / P) % P, pz = vox / (P * P);

    const u64* inb = (const u64*)(g_xp + (size_t)b * Din * Din * Din);
    const int ib2  = (((2 * pz) * Din + 2 * py) * Din + 2 * px) >> 1;

    u64 A[16], Bv[16], M[16];
    #pragma unroll
    for (int a = 0; a < 4; ++a)
        #pragma unroll
        for (int r = 0; r < 4; ++r) {
            const int o = ib2 + ((((a)*Din + r) * Din) >> 1);
            A[a * 4 + r]  = inb[o];
            Bv[a * 4 + r] = inb[o + 1];
        }
    #pragma unroll
    for (int i = 0; i < 16; ++i) M[i] = midp(A[i], Bv[i]);

    #pragma unroll 1
    for (int c = 0; c < 32; ++c) {
        const float bi = s_bias[c];
        u64 acc[4];
        #pragma unroll
        for (int j = 0; j < 4; ++j) acc[j] = pk2(bi, bi);

        const u64* wp = s_w + c * 27;
        #pragma unroll
        for (int tap = 0; tap < 27; ++tap) {
            const int kd = tap / 9, kh = (tap / 3) % 3, kw = tap % 3;
            const u64 ww = wp[tap];
            #pragma unroll
            for (int dz = 0; dz < 2; ++dz)
                #pragma unroll
                for (int dy = 0; dy < 2; ++dy) {
                    const int ri = (dz + kd) * 4 + dy + kh;
                    const u64 src = (kw == 0) ? A[ri] : (kw == 2) ? Bv[ri] : M[ri];
                    ffma2(acc[dz * 2 + dy], ww, src);
                }
        }

        float mv = -FLT_MAX;
        #pragma unroll
        for (int j = 0; j < 4; ++j) {
            float y0, y1; up2(acc[j], y0, y1);
            mv = fmaxf(mv, pointwise(y0, s_coef + c * 11, s_w1[c], s_w2[c], s_scale[c], s_beta[c]));
            mv = fmaxf(mv, pointwise(y1, s_coef + c * 11, s_w1[c], s_w2[c], s_scale[c], s_beta[c]));
        }
        out[((((size_t)b * 32 + c) * Pq + pz + 1) * Pq + py + 1) * Pq + px + 1] = mv;
    }
}

// --- Generic fused block (blocks 2 & 3): R2 weight path + L1 prefetch -------
template<int CIN, int D, int CTILE, int COUT, bool PADOUT>
__global__ void __launch_bounds__(128)
conv_block(const float* __restrict__ in,     // padded [2,CIN,(D+2)^3]
           const float* __restrict__ cw,     // [COUT,CIN,27]
           const float* __restrict__ cb,
           const float* __restrict__ w1p, const float* __restrict__ w2p,
           const float* __restrict__ gp,  const float* __restrict__ bp,
           float* __restrict__ out, int coefBase)
{
    constexpr int Din = D + 2;
    constexpr int P = D / 2, Pq = P + 2, NV = P * P * P;
    constexpr int CH_STRIDE2 = (Din * Din * Din) >> 1;   // u64 units

    const int cobase = blockIdx.y * CTILE;
    const int b      = blockIdx.z;

    __shared__ float  s_w[CIN * 27 * CTILE];   // [ci][tap][t]
    __shared__ float4 s_coef[CTILE * 11];
    __shared__ float  s_bias[CTILE], s_w1[CTILE], s_w2[CTILE],
                      s_scale[CTILE], s_beta[CTILE];

    for (int i = threadIdx.x; i < CIN * 27 * CTILE; i += 128) {
        const int t   = i % CTILE;
        const int tap = (i / CTILE) % 27;
        const int ci  = i / (CTILE * 27);
        s_w[i] = cw[((size_t)(cobase + t) * CIN + ci) * 27 + tap];
    }
    for (int i = threadIdx.x; i < CTILE * 11; i += 128)
        s_coef[i] = g_coef[(coefBase + cobase) * 11 + i];
    if (threadIdx.x < CTILE) {
        const int c = cobase + threadIdx.x;
        s_bias[threadIdx.x]  = cb[c];
        s_w1[threadIdx.x]    = w1p[c];
        s_w2[threadIdx.x]    = w2p[c];
        s_scale[threadIdx.x] = gp[c] * rsqrtf(1.0f + 1e-5f);
        s_beta[threadIdx.x]  = bp[c];
    }
    __syncthreads();

    const int vox = blockIdx.x * 128 + threadIdx.x;
    const int px = vox % P, py = (vox / P) % P, pz = vox / (P * P);

    u64 acc[CTILE][4];
    #pragma unroll
    for (int t = 0; t < CTILE; ++t) {
        const float bi = s_bias[t];
        const u64 bb = pk2(bi, bi);
        #pragma unroll
        for (int j = 0; j < 4; ++j) acc[t][j] = bb;
    }

    const u64* inb = (const u64*)(in + (size_t)b * CIN * Din * Din * Din);
    int ib2 = (((2 * pz) * Din + 2 * py) * Din + 2 * px) >> 1;

    #pragma unroll 1
    for (int ci = 0; ci < CIN; ++ci) {
        u64 A[16], Bv[16], M[16];
        #pragma unroll
        for (int a = 0; a < 4; ++a)
            #pragma unroll
            for (int r = 0; r < 4; ++r) {
                const int o = ib2 + (((a * Din + r) * Din) >> 1);
                A[a * 4 + r]  = inb[o];
                Bv[a * 4 + r] = inb[o + 1];
            }

        // Prefetch next channel's patch into L1 (register-free latency hiding).
        if (ci + 1 < CIN) {
            const int ibn = ib2 + CH_STRIDE2;
            #pragma unroll
            for (int a = 0; a < 4; ++a)
                #pragma unroll
                for (int r = 0; r < 4; ++r)
                    pf_l1(inb + ibn + (((a * Din + r) * Din) >> 1));
        }

        #pragma unroll
        for (int i = 0; i < 16; ++i) M[i] = midp(A[i], Bv[i]);

        const float* wp = s_w + ci * 27 * CTILE;
        #pragma unroll
        for (int tap = 0; tap < 27; ++tap) {
            const int kd = tap / 9, kh = (tap / 3) % 3, kw = tap % 3;
            const float4 wv = *(const float4*)(wp + tap * CTILE);  // CTILE==4
            #pragma unroll
            for (int t = 0; t < CTILE; ++t) {
                const float w = (t == 0) ? wv.x : (t == 1) ? wv.y : (t == 2) ? wv.z : wv.w;
                const u64 ww = pk2(w, w);
                #pragma unroll
                for (int dz = 0; dz < 2; ++dz)
                    #pragma unroll
                    for (int dy = 0; dy < 2; ++dy) {
                        const int ri = (dz + kd) * 4 + dy + kh;
                        const u64 src = (kw == 0) ? A[ri] : (kw == 2) ? Bv[ri] : M[ri];
                        ffma2(acc[t][dz * 2 + dy], ww, src);
                    }
            }
        }
        ib2 += CH_STRIDE2;
    }

    #pragma unroll
    for (int t = 0; t < CTILE; ++t) {
        float mv = -FLT_MAX;
        #pragma unroll
        for (int j = 0; j < 4; ++j) {
            float y0, y1; up2(acc[t][j], y0, y1);
            mv = fmaxf(mv, pointwise(y0, s_coef + t * 11, s_w1[t], s_w2[t], s_scale[t], s_beta[t]));
            mv = fmaxf(mv, pointwise(y1, s_coef + t * 11, s_w1[t], s_w2[t], s_scale[t], s_beta[t]));
        }
        const int c = cobase + t;
        if (PADOUT)
            out[((((size_t)b * COUT + c) * Pq + pz + 1) * Pq + py + 1) * Pq + px + 1] = mv;
        else
            out[((size_t)b * COUT + c) * NV + vox] = mv;
    }
}

// --- Head --------------------------------------------------------------------
__global__ void __launch_bounds__(64)
mean_kernel(const float* __restrict__ s3)
{
    const int bc = blockIdx.x;
    const int t  = threadIdx.x;
    const float* p = s3 + (size_t)bc * 512;

    float s = 0.0f;
    #pragma unroll
    for (int i = 0; i < 8; ++i) s += p[t + i * 64];
    #pragma unroll
    for (int off = 16; off > 0; off >>= 1)
        s += __shfl_down_sync(0xffffffffu, s, off);
    __shared__ float part[2];
    if ((t & 31) == 0) part[t >> 5] = s;
    __syncthreads();
    if (t == 0) g_mean[bc] = (part[0] + part[1]) * (1.0f / 512.0f);
}

__global__ void __launch_bounds__(256)
fc_kernel(const float* __restrict__ fc1w, const float* __restrict__ fc1b,
          const float* __restrict__ fc2w, const float* __restrict__ fc2b,
          float* __restrict__ out)
{
    const int t = threadIdx.x;
    __shared__ float m[2][128];
    __shared__ float h[2][256];

    if (t < 128) { m[0][t] = g_mean[t]; m[1][t] = g_mean[128 + t]; }
    __syncthreads();

    #pragma unroll
    for (int b = 0; b < 2; ++b) {
        float s = fc1b[t];
        const float* w = fc1w + t * 128;
        #pragma unroll 8
        for (int k = 0; k < 128; ++k) s = fmaf(m[b][k], w[k], s);
        h[b][t] = fmaxf(s, 0.0f);
    }
    __syncthreads();

    if (t < 4) {
        const int b = t >> 1, o = t & 1;
        float s = fc2b[o];
        const float* w = fc2w + o * 256;
        #pragma unroll 8
        for (int k = 0; k < 256; ++k) s = fmaf(h[b][k], w[k], s);
        out[b * 2 + o] = s;
    }
}

extern "C" void kernel_launch(void* const* d_in, const int* in_sizes, int n_in,
                              void* d_out, int out_size)
{
    (void)in_sizes; (void)n_in; (void)out_size;

    const float* x     = (const float*)d_in[0];
    const float* c1_w  = (const float*)d_in[1];
    const float* c1_b  = (const float*)d_in[2];
    const float* c1_k  = (const float*)d_in[3];
    const float* c1_sw = (const float*)d_in[4];
    const float* c1_w1 = (const float*)d_in[5];
    const float* c1_w2 = (const float*)d_in[6];
    const float* bn1_g = (const float*)d_in[7];
    const float* bn1_b = (const float*)d_in[8];
    const float* c2_w  = (const float*)d_in[9];
    const float* c2_b  = (const float*)d_in[10];
    const float* c2_k  = (const float*)d_in[11];
    const float* c2_sw = (const float*)d_in[12];
    const float* c2_w1 = (const float*)d_in[13];
    const float* c2_w2 = (const float*)d_in[14];
    const float* bn2_g = (const float*)d_in[15];
    const float* bn2_b = (const float*)d_in[16];
    const float* c3_w  = (const float*)d_in[17];
    const float* c3_b  = (const float*)d_in[18];
    const float* c3_k  = (const float*)d_in[19];
    const float* c3_sw = (const float*)d_in[20];
    const float* c3_w1 = (const float*)d_in[21];
    const float* c3_w2 = (const float*)d_in[22];
    const float* bn3_g = (const float*)d_in[23];
    const float* bn3_b = (const float*)d_in[24];
    const float* fc1_w = (const float*)d_in[25];
    const float* fc1_b = (const float*)d_in[26];
    const float* fc2_w = (const float*)d_in[27];
    const float* fc2_b = (const float*)d_in[28];
    float* out = (float*)d_out;

    float *s1p, *s2p, *s3;
    cudaGetSymbolAddress((void**)&s1p, g_s1p);
    cudaGetSymbolAddress((void**)&s2p, g_s2p);
    cudaGetSymbolAddress((void**)&s3,  g_s3);

    coef_kernel<<<1, 224>>>(c1_k, c1_sw, c2_k, c2_sw, c3_k, c3_sw);
    pad_x_kernel<<<(2 * 262144 + 255) / 256, 256>>>(x);

    block1_kernel<<<dim3(32768 / 128, 1, 2), 128>>>(
        c1_w, c1_b, c1_w1, c1_w2, bn1_g, bn1_b, s1p);

    conv_block<32, 32, 4, 64, true><<<dim3(4096 / 128, 64 / 4, 2), 128>>>(
        s1p, c2_w, c2_b, c2_w1, c2_w2, bn2_g, bn2_b, s2p, 32);

    conv_block<64, 16, 4, 128, false><<<dim3(512 / 128, 128 / 4, 2), 128>>>(
        s2p, c3_w, c3_b, c3_w1, c3_w2, bn3_g, bn3_b, s3, 96);

    mean_kernel<<<256, 64>>>(s3);
    fc_kernel<<<1, 256>>>(fc1_w, fc1_b, fc2_w, fc2_b, out);
}

// round 7
// speedup vs baseline: 1.1301x; 1.0450x over previous
#include <cuda_runtime.h>
#include <math.h>
#include <float.h>
#include <stdint.h>

// ---------------------------------------------------------------------------
// ConvKAN3D fused pipeline, R6:
//  - R5 design (cp.async double-buffered smem staging, 8x4x4 pooled CTA tile)
//  - FIX: block3 compact output indexing used (P/2)^3 after the P-refactor;
//    must be P^3 (P = pooled dim). This was the sole R5 correctness bug.
// ---------------------------------------------------------------------------

using u64 = unsigned long long;

__device__ __forceinline__ u64 pk2(float lo, float hi) {
    u64 r; asm("mov.b64 %0,{%1,%2};" : "=l"(r) : "f"(lo), "f"(hi)); return r;
}
__device__ __forceinline__ void up2(u64 v, float& lo, float& hi) {
    asm("mov.b64 {%0,%1}, %2;" : "=f"(lo), "=f"(hi) : "l"(v));
}
__device__ __forceinline__ void ffma2(u64& d, u64 a, u64 b) {
    asm("fma.rn.f32x2 %0, %1, %2, %0;" : "+l"(d) : "l"(a), "l"(b));
}
__device__ __forceinline__ u64 midp(u64 A, u64 B) {
    float al, ah, bl, bh; up2(A, al, ah); up2(B, bl, bh); return pk2(ah, bl);
}
__device__ __forceinline__ void cpa16(uint32_t dst, const float* src) {
    asm volatile("cp.async.ca.shared.global [%0], [%1], 16;" :: "r"(dst), "l"(src));
}
__device__ __forceinline__ void cpa_commit() {
    asm volatile("cp.async.commit_group;");
}
template<int N>
__device__ __forceinline__ void cpa_wait() {
    asm volatile("cp.async.wait_group %0;" :: "n"(N));
}

// Padded scratch (zero-initialized device globals; halos never written).
// s1p: [2,32,36,36,36]  (interior at 1..32, rest zero)
// s2p: [2,64,20,20,20]  (interior at 1..16, rest zero)
__device__ __align__(16) float g_xp [2u * 66u * 66u * 66u];              // 2.3 MB
__device__ __align__(16) float g_s1p[2u * 32u * 36u * 36u * 36u];        // 11.9 MB
__device__ __align__(16) float g_s2p[2u * 64u * 20u * 20u * 20u];        // 4.1 MB
__device__ __align__(16) float g_s3 [2u * 128u * 512u];                  // 0.5 MB
__device__ float4 g_coef[224 * 11];
__device__ float  g_mean[2 * 128];

// --- piecewise cubic coefficients -------------------------------------------
__global__ void coef_kernel(const float* __restrict__ k1, const float* __restrict__ sw1,
                            const float* __restrict__ k2, const float* __restrict__ sw2,
                            const float* __restrict__ k3, const float* __restrict__ sw3)
{
    const int t = threadIdx.x;
    if (t >= 224) return;
    const float* kn; const float* sw;
    if (t < 32)       { kn = k1; sw = sw1 + t * 10; }
    else if (t < 96)  { kn = k2; sw = sw2 + (t - 32) * 10; }
    else              { kn = k3; sw = sw3 + (t - 96) * 10; }

    float4 a = make_float4(0.f, 0.f, 0.f, 0.f);
    g_coef[t * 11 + 0] = a;
    for (int e = 1; e <= 10; ++e) {
        const float tk = kn[e - 1];
        const float s  = sw[e - 1];
        a.x = fmaf(-s * tk * tk, tk, a.x);
        a.y = fmaf(3.f * s * tk, tk, a.y);
        a.z = fmaf(-3.f * s, tk, a.z);
        a.w += s;
        g_coef[t * 11 + e] = a;
    }
}

// --- copy x into padded buffer ----------------------------------------------
__global__ void pad_x_kernel(const float* __restrict__ x)
{
    const int idx = blockIdx.x * blockDim.x + threadIdx.x;   // 2*64^3
    if (idx >= 2 * 262144) return;
    const int ix = idx & 63, iy = (idx >> 6) & 63, iz = (idx >> 12) & 63;
    const int b  = idx >> 18;
    g_xp[(((size_t)b * 66 + iz + 1) * 66 + iy + 1) * 66 + ix + 1] = x[idx];
}

// --- pointwise epilogue helper ----------------------------------------------
__device__ __forceinline__ float pointwise(float y, const float4* coef,
                                           float w1, float w2, float scale, float beta)
{
    int e = __float2int_rd((y + 1.0f) * 4.5f) + 1;
    e = max(0, min(10, e));
    const float4 cf = coef[e];
    const float sp  = fmaf(fmaf(fmaf(cf.w, y, cf.z), y, cf.y), y, cf.x);
    const float sig = 1.0f / (1.0f + __expf(-y));
    return fmaf(w1 * sp + w2 * (y * sig), scale, beta);
}

// --- Block 1: CIN=1, all 32 channels per thread ------------------------------
__global__ void __launch_bounds__(128)
block1_kernel(const float* __restrict__ cw,   // [32,1,27]
              const float* __restrict__ cb,
              const float* __restrict__ w1p, const float* __restrict__ w2p,
              const float* __restrict__ gp,  const float* __restrict__ bp,
              float* __restrict__ out)        // padded [2,32,36^3]
{
    constexpr int Din = 66, P = 32, SO = 36;

    __shared__ u64    s_w[32 * 27];            // packed {w,w}
    __shared__ float4 s_coef[32 * 11];
    __shared__ float  s_bias[32], s_w1[32], s_w2[32], s_scale[32], s_beta[32];

    for (int i = threadIdx.x; i < 32 * 27; i += 128) {
        const float w = cw[i];
        s_w[i] = pk2(w, w);
    }
    for (int i = threadIdx.x; i < 32 * 11; i += 128) s_coef[i] = g_coef[i];
    if (threadIdx.x < 32) {
        const int c = threadIdx.x;
        s_bias[c]  = cb[c];  s_w1[c] = w1p[c];  s_w2[c] = w2p[c];
        s_scale[c] = gp[c] * rsqrtf(1.0f + 1e-5f);  s_beta[c] = bp[c];
    }
    __syncthreads();

    const int vox = blockIdx.x * 128 + threadIdx.x;   // 0..32767
    const int b   = blockIdx.z;
    const int px = vox % P, py = (vox / P) % P, pz = vox / (P * P);

    const u64* inb = (const u64*)(g_xp + (size_t)b * Din * Din * Din);
    const int ib2  = (((2 * pz) * Din + 2 * py) * Din + 2 * px) >> 1;

    u64 A[16], Bv[16], M[16];
    #pragma unroll
    for (int a = 0; a < 4; ++a)
        #pragma unroll
        for (int r = 0; r < 4; ++r) {
            const int o = ib2 + ((((a)*Din + r) * Din) >> 1);
            A[a * 4 + r]  = inb[o];
            Bv[a * 4 + r] = inb[o + 1];
        }
    #pragma unroll
    for (int i = 0; i < 16; ++i) M[i] = midp(A[i], Bv[i]);

    #pragma unroll 1
    for (int c = 0; c < 32; ++c) {
        const float bi = s_bias[c];
        u64 acc[4];
        #pragma unroll
        for (int j = 0; j < 4; ++j) acc[j] = pk2(bi, bi);

        const u64* wp = s_w + c * 27;
        #pragma unroll
        for (int tap = 0; tap < 27; ++tap) {
            const int kd = tap / 9, kh = (tap / 3) % 3, kw = tap % 3;
            const u64 ww = wp[tap];
            #pragma unroll
            for (int dz = 0; dz < 2; ++dz)
                #pragma unroll
                for (int dy = 0; dy < 2; ++dy) {
                    const int ri = (dz + kd) * 4 + dy + kh;
                    const u64 src = (kw == 0) ? A[ri] : (kw == 2) ? Bv[ri] : M[ri];
                    ffma2(acc[dz * 2 + dy], ww, src);
                }
        }

        float mv = -FLT_MAX;
        #pragma unroll
        for (int j = 0; j < 4; ++j) {
            float y0, y1; up2(acc[j], y0, y1);
            mv = fmaxf(mv, pointwise(y0, s_coef + c * 11, s_w1[c], s_w2[c], s_scale[c], s_beta[c]));
            mv = fmaxf(mv, pointwise(y1, s_coef + c * 11, s_w1[c], s_w2[c], s_scale[c], s_beta[c]));
        }
        out[((((size_t)b * 32 + c) * SO + pz + 1) * SO + py + 1) * SO + px + 1] = mv;
    }
}

// --- Blocks 2 & 3: cp.async smem-staged fused conv block --------------------
// CTA = 8x4x4 pooled tile, 128 threads, CTILE=4 output channels.
// Input region per ci: 18x10x10 from padded [SIN^3] tensor, staged as
// 10x10 rows x 20 floats (5 float4 per row = 500 cp.async.16 per buffer).
// P = pooled output dim; SOUT > 0 -> padded output (stride SOUT), else compact P^3.
template<int CIN, int P, int SIN, int SOUT, int COUT>
__global__ void __launch_bounds__(128)
conv_block(const float* __restrict__ in,     // padded [2,CIN,SIN^3]
           const float* __restrict__ cw,     // [COUT,CIN,27]
           const float* __restrict__ cb,
           const float* __restrict__ w1p, const float* __restrict__ w2p,
           const float* __restrict__ gp,  const float* __restrict__ bp,
           float* __restrict__ out, int coefBase)
{
    constexpr int CTILE  = 4;
    constexpr int TRS    = 20;                 // tile row stride (floats)
    constexpr int TILE_F = 10 * 10 * TRS;      // 2000 floats per buffer
    constexpr int NTX = P / 8, NTY = P / 4;

    const int cobase = blockIdx.y * CTILE;
    const int b      = blockIdx.z;
    const int tx =  blockIdx.x % NTX;
    const int ty = (blockIdx.x / NTX) % NTY;
    const int tz =  blockIdx.x / (NTX * NTY);
    const int x0 = 16 * tx, y0 = 8 * ty, z0 = 8 * tz;   // padded input origin

    __shared__ float  s_w[CIN * 27 * CTILE];   // [ci][tap][t]
    __shared__ __align__(16) float s_tile[2][TILE_F];
    __shared__ float4 s_coef[CTILE * 11];
    __shared__ float  s_bias[CTILE], s_w1[CTILE], s_w2[CTILE],
                      s_scale[CTILE], s_beta[CTILE];

    const int tid = threadIdx.x;

    for (int i = tid; i < CIN * 27 * CTILE; i += 128) {
        const int t   = i % CTILE;
        const int tap = (i / CTILE) % 27;
        const int ci  = i / (CTILE * 27);
        s_w[i] = cw[((size_t)(cobase + t) * CIN + ci) * 27 + tap];
    }
    for (int i = tid; i < CTILE * 11; i += 128)
        s_coef[i] = g_coef[(coefBase + cobase) * 11 + i];
    if (tid < CTILE) {
        const int c = cobase + tid;
        s_bias[tid]  = cb[c];
        s_w1[tid]    = w1p[c];
        s_w2[tid]    = w2p[c];
        s_scale[tid] = gp[c] * rsqrtf(1.0f + 1e-5f);
        s_beta[tid]  = bp[c];
    }

    // Precompute loop-invariant cp.async offsets (4 fragments per thread).
    const float* chan0 = in + (size_t)b * CIN * SIN * SIN * SIN;
    int      soff[4];
    uint32_t doff[4];
    bool     sval[4];
    #pragma unroll
    for (int k = 0; k < 4; ++k) {
        const int f = tid + k * 128;
        sval[k] = (f < 500);
        const int fc  = sval[k] ? f : 0;
        const int row = fc / 5, xf = fc % 5;
        const int zr  = row / 10, yr = row % 10;
        soff[k] = ((z0 + zr) * SIN + (y0 + yr)) * SIN + x0 + xf * 4;
        doff[k] = (uint32_t)__cvta_generic_to_shared(
                      &s_tile[0][(zr * 10 + yr) * TRS + xf * 4]);
    }
    constexpr int CH_STRIDE = SIN * SIN * SIN;
    constexpr uint32_t BUF_BYTES = TILE_F * 4;

    // Prologue: stage ci=0 into buffer 0.
    #pragma unroll
    for (int k = 0; k < 4; ++k)
        if (sval[k]) cpa16(doff[k], chan0 + soff[k]);
    cpa_commit();

    const int lpx = tid & 7, lpy = (tid >> 3) & 3, lpz = tid >> 5;

    u64 acc[CTILE][4];
    #pragma unroll
    for (int t = 0; t < CTILE; ++t) {
        acc[t][0] = 0; acc[t][1] = 0; acc[t][2] = 0; acc[t][3] = 0;
    }

    #pragma unroll 1
    for (int ci = 0; ci < CIN; ++ci) {
        if (ci + 1 < CIN) {
            const float* src = chan0 + (size_t)(ci + 1) * CH_STRIDE;
            const uint32_t dadd = ((ci + 1) & 1) ? BUF_BYTES : 0u;
            #pragma unroll
            for (int k = 0; k < 4; ++k)
                if (sval[k]) cpa16(doff[k] + dadd, src + soff[k]);
            cpa_commit();
            cpa_wait<1>();
        } else {
            cpa_wait<0>();
        }
        __syncthreads();   // staged data visible to all threads; params staged

        if (ci == 0) {     // init accumulators with bias (params ready after barrier)
            #pragma unroll
            for (int t = 0; t < CTILE; ++t) {
                const u64 bb = pk2(s_bias[t], s_bias[t]);
                #pragma unroll
                for (int j = 0; j < 4; ++j) acc[t][j] = bb;
            }
        }

        const float* tp = s_tile[ci & 1];

        u64 A[16], Bv[16], M[16];
        #pragma unroll
        for (int a = 0; a < 4; ++a)
            #pragma unroll
            for (int r = 0; r < 4; ++r) {
                const float* rowp = tp + ((2 * lpz + a) * 10 + 2 * lpy + r) * TRS + 2 * lpx;
                A[a * 4 + r]  = *(const u64*)rowp;
                Bv[a * 4 + r] = *(const u64*)(rowp + 2);
            }
        #pragma unroll
        for (int i = 0; i < 16; ++i) M[i] = midp(A[i], Bv[i]);

        const float* wp = s_w + ci * 27 * CTILE;
        #pragma unroll
        for (int tap = 0; tap < 27; ++tap) {
            const int kd = tap / 9, kh = (tap / 3) % 3, kw = tap % 3;
            const float4 wv = *(const float4*)(wp + tap * CTILE);
            #pragma unroll
            for (int t = 0; t < CTILE; ++t) {
                const float w = (t == 0) ? wv.x : (t == 1) ? wv.y : (t == 2) ? wv.z : wv.w;
                const u64 ww = pk2(w, w);
                #pragma unroll
                for (int dz = 0; dz < 2; ++dz)
                    #pragma unroll
                    for (int dy = 0; dy < 2; ++dy) {
                        const int ri = (dz + kd) * 4 + dy + kh;
                        const u64 src = (kw == 0) ? A[ri] : (kw == 2) ? Bv[ri] : M[ri];
                        ffma2(acc[t][dz * 2 + dy], ww, src);
                    }
            }
        }
        __syncthreads();   // done reading this buffer before it is re-staged
    }

    // pooled output coordinates
    const int gpx = 8 * tx + lpx, gpy = 4 * ty + lpy, gpz = 4 * tz + lpz;

    #pragma unroll
    for (int t = 0; t < CTILE; ++t) {
        float mv = -FLT_MAX;
        #pragma unroll
        for (int j = 0; j < 4; ++j) {
            float y0v, y1v; up2(acc[t][j], y0v, y1v);
            mv = fmaxf(mv, pointwise(y0v, s_coef + t * 11, s_w1[t], s_w2[t], s_scale[t], s_beta[t]));
            mv = fmaxf(mv, pointwise(y1v, s_coef + t * 11, s_w1[t], s_w2[t], s_scale[t], s_beta[t]));
        }
        const int c = cobase + t;
        if (SOUT > 0)
            out[((((size_t)b * COUT + c) * SOUT + gpz + 1) * SOUT + gpy + 1) * SOUT + gpx + 1] = mv;
        else  // compact [2, COUT, P^3]  (FIXED: was (P/2)^3)
            out[((size_t)b * COUT + c) * (P * P * P) + (gpz * P + gpy) * P + gpx] = mv;
    }
}

// --- Head --------------------------------------------------------------------
__global__ void __launch_bounds__(64)
mean_kernel(const float* __restrict__ s3)
{
    const int bc = blockIdx.x;
    const int t  = threadIdx.x;
    const float* p = s3 + (size_t)bc * 512;

    float s = 0.0f;
    #pragma unroll
    for (int i = 0; i < 8; ++i) s += p[t + i * 64];
    #pragma unroll
    for (int off = 16; off > 0; off >>= 1)
        s += __shfl_down_sync(0xffffffffu, s, off);
    __shared__ float part[2];
    if ((t & 31) == 0) part[t >> 5] = s;
    __syncthreads();
    if (t == 0) g_mean[bc] = (part[0] + part[1]) * (1.0f / 512.0f);
}

__global__ void __launch_bounds__(256)
fc_kernel(const float* __restrict__ fc1w, const float* __restrict__ fc1b,
          const float* __restrict__ fc2w, const float* __restrict__ fc2b,
          float* __restrict__ out)
{
    const int t = threadIdx.x;
    __shared__ float m[2][128];
    __shared__ float h[2][256];

    if (t < 128) { m[0][t] = g_mean[t]; m[1][t] = g_mean[128 + t]; }
    __syncthreads();

    #pragma unroll
    for (int b = 0; b < 2; ++b) {
        float s = fc1b[t];
        const float* w = fc1w + t * 128;
        #pragma unroll 8
        for (int k = 0; k < 128; ++k) s = fmaf(m[b][k], w[k], s);
        h[b][t] = fmaxf(s, 0.0f);
    }
    __syncthreads();

    if (t < 4) {
        const int b = t >> 1, o = t & 1;
        float s = fc2b[o];
        const float* w = fc2w + o * 256;
        #pragma unroll 8
        for (int k = 0; k < 256; ++k) s = fmaf(h[b][k], w[k], s);
        out[b * 2 + o] = s;
    }
}

extern "C" void kernel_launch(void* const* d_in, const int* in_sizes, int n_in,
                              void* d_out, int out_size)
{
    (void)in_sizes; (void)n_in; (void)out_size;

    const float* x     = (const float*)d_in[0];
    const float* c1_w  = (const float*)d_in[1];
    const float* c1_b  = (const float*)d_in[2];
    const float* c1_k  = (const float*)d_in[3];
    const float* c1_sw = (const float*)d_in[4];
    const float* c1_w1 = (const float*)d_in[5];
    const float* c1_w2 = (const float*)d_in[6];
    const float* bn1_g = (const float*)d_in[7];
    const float* bn1_b = (const float*)d_in[8];
    const float* c2_w  = (const float*)d_in[9];
    const float* c2_b  = (const float*)d_in[10];
    const float* c2_k  = (const float*)d_in[11];
    const float* c2_sw = (const float*)d_in[12];
    const float* c2_w1 = (const float*)d_in[13];
    const float* c2_w2 = (const float*)d_in[14];
    const float* bn2_g = (const float*)d_in[15];
    const float* bn2_b = (const float*)d_in[16];
    const float* c3_w  = (const float*)d_in[17];
    const float* c3_b  = (const float*)d_in[18];
    const float* c3_k  = (const float*)d_in[19];
    const float* c3_sw = (const float*)d_in[20];
    const float* c3_w1 = (const float*)d_in[21];
    const float* c3_w2 = (const float*)d_in[22];
    const float* bn3_g = (const float*)d_in[23];
    const float* bn3_b = (const float*)d_in[24];
    const float* fc1_w = (const float*)d_in[25];
    const float* fc1_b = (const float*)d_in[26];
    const float* fc2_w = (const float*)d_in[27];
    const float* fc2_b = (const float*)d_in[28];
    float* out = (float*)d_out;

    float *s1p, *s2p, *s3;
    cudaGetSymbolAddress((void**)&s1p, g_s1p);
    cudaGetSymbolAddress((void**)&s2p, g_s2p);
    cudaGetSymbolAddress((void**)&s3,  g_s3);

    coef_kernel<<<1, 224>>>(c1_k, c1_sw, c2_k, c2_sw, c3_k, c3_sw);
    pad_x_kernel<<<(2 * 262144 + 255) / 256, 256>>>(x);

    // Block 1: CIN=1, D=64 -> s1p (stride-36 padded)
    block1_kernel<<<dim3(32768 / 128, 1, 2), 128>>>(
        c1_w, c1_b, c1_w1, c1_w2, bn1_g, bn1_b, s1p);

    // Block 2: CIN=32, P=16, SIN=36 -> s2p (stride-20 padded)
    conv_block<32, 16, 36, 20, 64><<<dim3(32, 16, 2), 128>>>(
        s1p, c2_w, c2_b, c2_w1, c2_w2, bn2_g, bn2_b, s2p, 32);

    // Block 3: CIN=64, P=8, SIN=20 -> s3 (compact 8^3)
    conv_block<64, 8, 20, 0, 128><<<dim3(4, 32, 2), 128>>>(
        s2p, c3_w, c3_b, c3_w1, c3_w2, bn3_g, bn3_b, s3, 96);

    mean_kernel<<<256, 64>>>(s3);
    fc_kernel<<<1, 256>>>(fc1_w, fc1_b, fc2_w, fc2_b, out);
}